// round 7
// baseline (speedup 1.0000x reference)
#include <cuda_runtime.h>
#include <cuda_fp16.h>
#include <math.h>

#define NNODES 50000
#define NEDGES 800000
#define CH_SCAN 512
#define NB_SCAN ((NNODES + CH_SCAN - 1) / CH_SCAN)   // 98

// ---------------- scratch (static device globals; no allocations) ----------
__device__ __half g_z[2 * NNODES * 256];     // fp16 per-etype GEMM output (layers 1,2)
__device__ float g_h1[NNODES * 128];
__device__ __half g_h2h[NNODES * 64];        // fp16 h2 for MH gather
__device__ float g_el[2 * NNODES * 4];       // per-layer el (etype-major)
__device__ float g_er[2 * NNODES * 4];
__device__ float g_elm[2 * NNODES * 4];      // MH-layer el (separate: no race)
__device__ float g_erm[2 * NNODES * 4];
__device__ float g_aggm[NNODES * 512];       // MH aggregated h2: (N, head, et*64+k)
__device__ float g_wvec[16 * 64];            // projections for MH logits
__device__ float g_Bm[4 * 128 * 64];         // per-head combine matrix (0.5*Wm relayout)
__device__ float g_colsum[256];
__device__ int   g_rp[2][NNODES + 1];        // CSR row pointers (by dst)
__device__ int   g_cse[2][NEDGES];           // CSR src indices
__device__ int   g_wp[2][NNODES];            // fill cursors
__device__ int   g_bsum[2][128];             // scan block sums (raw)

// ---------------- f32x2 packed-FMA helpers ----------------
__device__ __forceinline__ unsigned long long bcast2(float v) {
    unsigned long long r;
    asm("mov.b64 %0, {%1, %1};" : "=l"(r) : "f"(v));
    return r;
}
__device__ __forceinline__ void ffma2(unsigned long long& d,
                                      unsigned long long a, unsigned long long b) {
    asm("fma.rn.f32x2 %0, %1, %2, %0;" : "+l"(d) : "l"(a), "l"(b));
}
__device__ __forceinline__ float2 unpack2(unsigned long long v) {
    float2 f;
    asm("mov.b64 {%0, %1}, %2;" : "=f"(f.x), "=f"(f.y) : "l"(v));
    return f;
}

__device__ __forceinline__ float lrelu(float v) {
    return (v > 0.0f) ? v : 0.2f * v;
}
__device__ __forceinline__ float2 h2f(const __half2 h) { return __half22float2(h); }

// ---------------- small utility kernels ----------------
__global__ void zero_int(int* p, int n) {
    int i = blockIdx.x * blockDim.x + threadIdx.x;
    if (i < n) p[i] = 0;
}
__global__ void zero_f(float* p, int n) {
    int i = blockIdx.x * blockDim.x + threadIdx.x;
    if (i < n) p[i] = 0.0f;
}

// ---------------- MH precompute: wvec = Wm @ a{l,r}m ; Bm relayout ----------
__global__ void prep_mh(const float* __restrict__ Wm, const float* __restrict__ alm,
                        const float* __restrict__ arm,
                        float* __restrict__ wvec, float* __restrict__ Bm) {
    int t = threadIdx.x;            // 512 threads: (et, h, k)
    int et = t >> 8;
    int h = (t >> 6) & 3;
    int k = t & 63;
    const float* wrow = Wm + et * 64 * 256 + k * 256 + h * 64;   // 64 f's contiguous
    const float* av = alm + et * 256 + h * 64;
    const float* rv = arm + et * 256 + h * 64;
    float sl = 0.0f, sr = 0.0f;
    float* brow = Bm + h * (128 * 64) + (et * 64 + k) * 64;
#pragma unroll
    for (int f = 0; f < 64; f += 4) {
        float4 w4 = *(const float4*)&wrow[f];
        float4 a4 = *(const float4*)&av[f];
        float4 r4 = *(const float4*)&rv[f];
        sl += w4.x * a4.x + w4.y * a4.y + w4.z * a4.z + w4.w * a4.w;
        sr += w4.x * r4.x + w4.y * r4.y + w4.z * r4.z + w4.w * r4.w;
        float4 b4 = {0.5f * w4.x, 0.5f * w4.y, 0.5f * w4.z, 0.5f * w4.w};
        *(float4*)&brow[f] = b4;
    }
    wvec[(et * 8 + h) * 64 + k] = sl;         // v = et*8 + 0 + h  (el)
    wvec[(et * 8 + 4 + h) * 64 + k] = sr;     // v = et*8 + 4 + h  (er)
}

// ---------------- CSR build pieces ----------------
__global__ void scan_local(int* __restrict__ rpb, int* __restrict__ bsumb) {
    __shared__ int s[CH_SCAN];
    int* rp = rpb + blockIdx.y * (NNODES + 1);
    int* bsum = bsumb + blockIdx.y * 128;
    int tid = threadIdx.x;
    int i = blockIdx.x * CH_SCAN + tid;
    int v = (i < NNODES) ? rp[i] : 0;
    s[tid] = v;
    __syncthreads();
    for (int off = 1; off < CH_SCAN; off <<= 1) {
        int t = (tid >= off) ? s[tid - off] : 0;
        __syncthreads();
        s[tid] += t;
        __syncthreads();
    }
    if (i < NNODES) rp[i] = s[tid] - v;
    if (tid == CH_SCAN - 1) bsum[blockIdx.x] = s[tid];
}

__global__ void scan_add_wp(int* __restrict__ rpb, const int* __restrict__ bsumb,
                            int* __restrict__ wpb) {
    __shared__ int sb[128];
    int tid = threadIdx.x;
    if (tid < 128) {
        int v = (tid < NB_SCAN) ? bsumb[blockIdx.y * 128 + tid] : 0;
        sb[tid] = v;
    }
    __syncthreads();
    for (int off = 1; off < 128; off <<= 1) {
        int t = (tid < 128 && tid >= off) ? sb[tid - off] : 0;
        __syncthreads();
        if (tid < 128) sb[tid] += t;
        __syncthreads();
    }
    int i = blockIdx.x * blockDim.x + tid;
    int* rp = rpb + blockIdx.y * (NNODES + 1);
    int* wp = wpb + blockIdx.y * NNODES;
    if (i < NNODES) {
        int c = i / CH_SCAN;
        int pre = (c == 0) ? 0 : sb[c - 1];
        int v = rp[i] + pre;
        rp[i] = v;
        wp[i] = v;
    }
    if (i == 0) rp[NNODES] = NEDGES;
}

__global__ void fill_k(const int* __restrict__ s0, const int* __restrict__ s1,
                       const int* __restrict__ d0, const int* __restrict__ d1,
                       int* __restrict__ wpb, int* __restrict__ csb) {
    int e = blockIdx.x * blockDim.x + threadIdx.x;
    if (e >= NEDGES) return;
    const int* src = blockIdx.y ? s1 : s0;
    const int* dst = blockIdx.y ? d1 : d0;
    int* wp = wpb + blockIdx.y * NNODES;
    int* cs = csb + blockIdx.y * NEDGES;
    int p = atomicAdd(&wp[dst[e]], 1);
    cs[p] = src[e];
}

// ---------------- GEMM body (transposed X tile, f32x2 packed FMA) ----------
template <int K, int HF, int H>
__device__ __forceinline__ void
gemm_body(int bx, int by,
          const float* __restrict__ X, const float* __restrict__ Wb,
          const float* __restrict__ alb, const float* __restrict__ arb,
          __half* __restrict__ Zb, float* __restrict__ elb, float* __restrict__ erb) {
    constexpr int TN = 8, TM = 8, BK = 16;
    constexpr int TX = HF / TN;
    constexpr int TY = 256 / TX;
    constexpr int BM = TM * TY;
    constexpr int BMP = BM + 4;
    constexpr int RW = TX / H;

    __shared__ float xs[BK][BMP];
    __shared__ float ws[BK][HF];

    const float* W  = Wb  + by * K * HF;
    const float* al = alb + by * HF;
    const float* ar = arb + by * HF;
    __half* Z = Zb  + by * (NNODES * 256);
    float* el = elb + by * (NNODES * 4);
    float* er = erb + by * (NNODES * 4);

    int tid = threadIdx.x;
    int tx = tid % TX;
    int ty = tid / TX;
    int r0 = bx * BM;

    unsigned long long acc2[TM][TN / 2];
#pragma unroll
    for (int i = 0; i < TM; i++)
#pragma unroll
        for (int j = 0; j < TN / 2; j++) acc2[i][j] = 0ull;

    for (int kb = 0; kb < K; kb += BK) {
#pragma unroll
        for (int idx = tid; idx < BM * BK / 4; idx += 256) {
            int lin = idx * 4;
            int r = lin / BK, c = lin % BK;
            int gr = r0 + r;
            float4 v = make_float4(0.f, 0.f, 0.f, 0.f);
            if (gr < NNODES) v = *(const float4*)&X[gr * K + kb + c];
            xs[c][r] = v.x; xs[c + 1][r] = v.y; xs[c + 2][r] = v.z; xs[c + 3][r] = v.w;
        }
#pragma unroll
        for (int idx = tid; idx < BK * HF / 4; idx += 256) {
            int lin = idx * 4;
            int r = lin / HF, c = lin % HF;
            *(float4*)&ws[r][c] = *(const float4*)&W[(kb + r) * HF + c];
        }
        __syncthreads();
#pragma unroll
        for (int kk = 0; kk < BK; kk++) {
            float4 a0 = *(const float4*)&xs[kk][ty * 8];
            float4 a1 = *(const float4*)&xs[kk][ty * 8 + 4];
            const unsigned long long* wp64 =
                (const unsigned long long*)&ws[kk][tx * 8];
            unsigned long long bp0 = wp64[0], bp1 = wp64[1],
                               bp2 = wp64[2], bp3 = wp64[3];
            unsigned long long ap[TM] = {
                bcast2(a0.x), bcast2(a0.y), bcast2(a0.z), bcast2(a0.w),
                bcast2(a1.x), bcast2(a1.y), bcast2(a1.z), bcast2(a1.w)};
#pragma unroll
            for (int i = 0; i < TM; i++) {
                ffma2(acc2[i][0], ap[i], bp0);
                ffma2(acc2[i][1], ap[i], bp1);
                ffma2(acc2[i][2], ap[i], bp2);
                ffma2(acc2[i][3], ap[i], bp3);
            }
        }
        __syncthreads();
    }

    int cbase = tx * TN;
#pragma unroll
    for (int i = 0; i < TM; i++) {
        int row = r0 + ty * TM + i;
        float2 u0 = unpack2(acc2[i][0]);
        float2 u1 = unpack2(acc2[i][1]);
        float2 u2 = unpack2(acc2[i][2]);
        float2 u3 = unpack2(acc2[i][3]);
        float av[TN] = {u0.x, u0.y, u1.x, u1.y, u2.x, u2.y, u3.x, u3.y};
        float pl = 0.0f, pr = 0.0f;
#pragma unroll
        for (int j = 0; j < TN; j++) {
            pl += av[j] * al[cbase + j];
            pr += av[j] * ar[cbase + j];
        }
#pragma unroll
        for (int o = RW / 2; o > 0; o >>= 1) {
            pl += __shfl_xor_sync(0xffffffffu, pl, o);
            pr += __shfl_xor_sync(0xffffffffu, pr, o);
        }
        if (row < NNODES) {
            uint4 pack;
            __half2* ph = (__half2*)&pack;
            ph[0] = __floats2half2_rn(av[0], av[1]);
            ph[1] = __floats2half2_rn(av[2], av[3]);
            ph[2] = __floats2half2_rn(av[4], av[5]);
            ph[3] = __floats2half2_rn(av[6], av[7]);
            *(uint4*)&Z[row * HF + cbase] = pack;
            if (tx % RW == 0) {
                int h = tx / RW;
                el[row * H + h] = pl;
                er[row * H + h] = pr;
            }
        }
    }
}

template <int K, int HF, int H>
__global__ void __launch_bounds__(256)
gemm_att(const float* __restrict__ X, const float* __restrict__ Wb,
         const float* __restrict__ alb, const float* __restrict__ arb,
         __half* __restrict__ Zb, float* __restrict__ elb, float* __restrict__ erb) {
    gemm_body<K, HF, H>(blockIdx.x, blockIdx.y, X, Wb, alb, arb, Zb, elb, erb);
}

// layer-1 GEMM fused with independent CSR edge counting
__global__ void __launch_bounds__(256)
gemm1_count(const float* __restrict__ X, const float* __restrict__ Wb,
            const float* __restrict__ alb, const float* __restrict__ arb,
            __half* __restrict__ Zb, float* __restrict__ elb, float* __restrict__ erb,
            const int* __restrict__ d0, const int* __restrict__ d1,
            int* __restrict__ rpb, int gemmX, int countBlocks) {
    if ((int)blockIdx.x < gemmX) {
        gemm_body<128, 128, 1>(blockIdx.x, blockIdx.y, X, Wb, alb, arb, Zb, elb, erb);
    } else {
        int cb = blockIdx.x - gemmX;
        const int* dst = blockIdx.y ? d1 : d0;
        int* cnt = rpb + blockIdx.y * (NNODES + 1);
        for (int e = cb * 256 + threadIdx.x; e < NEDGES; e += countBlocks * 256)
            atomicAdd(&cnt[dst[e]], 1);
    }
}

// ---------------- layer-1 aggregation (HF=128, H=1) ----------------
__global__ void __launch_bounds__(256)
gat_agg128(const int* __restrict__ rp0, const int* __restrict__ cs0,
           const int* __restrict__ rp1, const int* __restrict__ cs1,
           const __half* __restrict__ z0, const __half* __restrict__ z1,
           const float* __restrict__ el0, const float* __restrict__ er0,
           const float* __restrict__ el1, const float* __restrict__ er1,
           const float* __restrict__ bia, float* __restrict__ out) {
    int w = (blockIdx.x * blockDim.x + threadIdx.x) >> 5;
    if (w >= NNODES) return;
    int lane = threadIdx.x & 31;

    float acc[4] = {0.f, 0.f, 0.f, 0.f};
#pragma unroll
    for (int et = 0; et < 2; et++) {
        const int* rp = et ? rp1 : rp0;
        const int* cs = et ? cs1 : cs0;
        const __half* z = et ? z1 : z0;
        const float* el = et ? el1 : el0;
        const float* er = et ? er1 : er0;

        int beg = rp[w];
        int end = rp[w + 1];
        if (beg == end) continue;

        float accE[4] = {0.f, 0.f, 0.f, 0.f};
        float ern = er[w];
        float den = 0.0f;
        int i = beg;
        for (; i + 4 <= end; i += 4) {
            int sa = cs[i], sb = cs[i + 1], sc = cs[i + 2], sd = cs[i + 3];
            float wa = __expf(lrelu(el[sa] + ern));
            float wb = __expf(lrelu(el[sb] + ern));
            float wc = __expf(lrelu(el[sc] + ern));
            float wd = __expf(lrelu(el[sd] + ern));
            uint2 pa = *(const uint2*)&z[sa * 128 + lane * 4];
            uint2 pb = *(const uint2*)&z[sb * 128 + lane * 4];
            uint2 pc = *(const uint2*)&z[sc * 128 + lane * 4];
            uint2 pd = *(const uint2*)&z[sd * 128 + lane * 4];
            float2 a0 = h2f(((const __half2*)&pa)[0]), a1 = h2f(((const __half2*)&pa)[1]);
            float2 b0 = h2f(((const __half2*)&pb)[0]), b1 = h2f(((const __half2*)&pb)[1]);
            float2 cc0 = h2f(((const __half2*)&pc)[0]), cc1 = h2f(((const __half2*)&pc)[1]);
            float2 d0 = h2f(((const __half2*)&pd)[0]), d1 = h2f(((const __half2*)&pd)[1]);
            accE[0] += wa * a0.x + wb * b0.x + wc * cc0.x + wd * d0.x;
            accE[1] += wa * a0.y + wb * b0.y + wc * cc0.y + wd * d0.y;
            accE[2] += wa * a1.x + wb * b1.x + wc * cc1.x + wd * d1.x;
            accE[3] += wa * a1.y + wb * b1.y + wc * cc1.y + wd * d1.y;
            den += wa + wb + wc + wd;
        }
        for (; i < end; i++) {
            int s = cs[i];
            float wt = __expf(lrelu(el[s] + ern));
            den += wt;
            uint2 p = *(const uint2*)&z[s * 128 + lane * 4];
            float2 f0 = h2f(((const __half2*)&p)[0]);
            float2 f1 = h2f(((const __half2*)&p)[1]);
            accE[0] += wt * f0.x; accE[1] += wt * f0.y;
            accE[2] += wt * f1.x; accE[3] += wt * f1.y;
        }
        float sc1 = 0.5f / fmaxf(den, 1e-30f);
#pragma unroll
        for (int j = 0; j < 4; j++) acc[j] += accE[j] * sc1;
    }

    int f = lane * 4;
    float4 o;
    o.x = acc[0] + 0.5f * (bia[f + 0] + bia[128 + f + 0]);
    o.y = acc[1] + 0.5f * (bia[f + 1] + bia[128 + f + 1]);
    o.z = acc[2] + 0.5f * (bia[f + 2] + bia[128 + f + 2]);
    o.w = acc[3] + 0.5f * (bia[f + 3] + bia[128 + f + 3]);
    *(float4*)&out[w * 128 + f] = o;
}

// ---------------- layer-2 aggregation + MH prep fused ----------------
// Gathers z2 (64-dim), produces h2h (fp16) and MH el/er via wvec projections.
__global__ void __launch_bounds__(256)
gat_agg64_prep(const int* __restrict__ rp0, const int* __restrict__ cs0,
               const int* __restrict__ rp1, const int* __restrict__ cs1,
               const __half* __restrict__ z0, const __half* __restrict__ z1,
               const float* __restrict__ el0, const float* __restrict__ er0,
               const float* __restrict__ el1, const float* __restrict__ er1,
               const float* __restrict__ bia, const float* __restrict__ fc,
               const float* __restrict__ wvec,
               __half* __restrict__ h2h,
               float* __restrict__ elmb, float* __restrict__ ermb) {
    int w = (blockIdx.x * blockDim.x + threadIdx.x) >> 5;
    if (w >= NNODES) return;
    int lane = threadIdx.x & 31;

    float c0 = 0.5f * (fc[0] + fc[2]);
    float c1 = 0.5f * (fc[1] + fc[3]);

    float acc[2] = {0.f, 0.f};
#pragma unroll
    for (int et = 0; et < 2; et++) {
        const int* rp = et ? rp1 : rp0;
        const int* cs = et ? cs1 : cs0;
        const __half* z = et ? z1 : z0;
        const float* el = et ? el1 : el0;
        const float* er = et ? er1 : er0;
        float ce = et ? c1 : c0;

        int beg = rp[w];
        int end = rp[w + 1];
        if (beg == end) continue;

        float accE[2] = {0.f, 0.f};
        float ern = er[w];
        float den = 0.0f;
        int i = beg;
        for (; i + 4 <= end; i += 4) {
            int sa = cs[i], sb = cs[i + 1], sc = cs[i + 2], sd = cs[i + 3];
            float wa = __expf(lrelu(el[sa] + ern));
            float wb = __expf(lrelu(el[sb] + ern));
            float wc = __expf(lrelu(el[sc] + ern));
            float wd = __expf(lrelu(el[sd] + ern));
            float2 a0 = h2f(*(const __half2*)&z[sa * 64 + lane * 2]);
            float2 b0 = h2f(*(const __half2*)&z[sb * 64 + lane * 2]);
            float2 cc0 = h2f(*(const __half2*)&z[sc * 64 + lane * 2]);
            float2 d0 = h2f(*(const __half2*)&z[sd * 64 + lane * 2]);
            accE[0] += wa * a0.x + wb * b0.x + wc * cc0.x + wd * d0.x;
            accE[1] += wa * a0.y + wb * b0.y + wc * cc0.y + wd * d0.y;
            den += wa + wb + wc + wd;
        }
        for (; i < end; i++) {
            int s = cs[i];
            float wt = __expf(lrelu(el[s] + ern));
            den += wt;
            float2 f0 = h2f(*(const __half2*)&z[s * 64 + lane * 2]);
            accE[0] += wt * f0.x; accE[1] += wt * f0.y;
        }
        float sc1 = ce / fmaxf(den, 1e-30f);
        acc[0] += accE[0] * sc1;
        acc[1] += accE[1] * sc1;
    }

    int f = lane * 2;
    float ox = acc[0] + c0 * bia[f] + c1 * bia[64 + f];
    float oy = acc[1] + c0 * bia[f + 1] + c1 * bia[64 + f + 1];
    // write fp16 h2 for the MH gather
    *(__half2*)&h2h[w * 64 + f] = __floats2half2_rn(ox, oy);

    // MH logits: 16 dot products h2 . wvec[v]
    float p[16];
#pragma unroll
    for (int v = 0; v < 16; v++) {
        float2 wv = *(const float2*)&wvec[v * 64 + f];
        p[v] = ox * wv.x + oy * wv.y;
    }
#pragma unroll
    for (int v = 0; v < 16; v++)
#pragma unroll
        for (int off = 16; off > 0; off >>= 1)
            p[v] += __shfl_xor_sync(0xffffffffu, p[v], off);
    if (lane == 0) {
        *(float4*)&elmb[w * 4] = make_float4(p[0], p[1], p[2], p[3]);
        *(float4*)&ermb[w * 4] = make_float4(p[4], p[5], p[6], p[7]);
        *(float4*)&elmb[NNODES * 4 + w * 4] = make_float4(p[8], p[9], p[10], p[11]);
        *(float4*)&ermb[NNODES * 4 + w * 4] = make_float4(p[12], p[13], p[14], p[15]);
    }
}

// ---------------- MH aggregation of raw h2 (64-dim gather) ----------------
// aggm[n, h, et*64+k] = sum_e alpha_{e,h} * h2h[src_e, k]   (per etype)
__global__ void __launch_bounds__(256)
gat_agg_mh(const int* __restrict__ rp0, const int* __restrict__ cs0,
           const int* __restrict__ rp1, const int* __restrict__ cs1,
           const __half* __restrict__ h2h,
           const float* __restrict__ elmb, const float* __restrict__ ermb,
           float* __restrict__ aggm) {
    int w = (blockIdx.x * blockDim.x + threadIdx.x) >> 5;
    if (w >= NNODES) return;
    int lane = threadIdx.x & 31;
    int half = lane >> 4;           // heads {half*2, half*2+1}
    int l = lane & 15;              // k = l*4 .. l*4+3

#pragma unroll
    for (int et = 0; et < 2; et++) {
        const int* rp = et ? rp1 : rp0;
        const int* cs = et ? cs1 : cs0;
        const float* elm = elmb + et * NNODES * 4;
        const float* erm = ermb + et * NNODES * 4;

        float a0[4] = {0.f, 0.f, 0.f, 0.f};    // head half*2
        float a1[4] = {0.f, 0.f, 0.f, 0.f};    // head half*2+1
        float den0 = 0.0f, den1 = 0.0f;

        int beg = rp[w];
        int end = rp[w + 1];
        if (beg != end) {
            float2 ern = *(const float2*)&erm[w * 4 + half * 2];
            int i = beg;
            for (; i + 2 <= end; i += 2) {
                int sa = cs[i], sb = cs[i + 1];
                float2 ea = *(const float2*)&elm[sa * 4 + half * 2];
                float2 eb = *(const float2*)&elm[sb * 4 + half * 2];
                uint2 pa = *(const uint2*)&h2h[sa * 64 + l * 4];
                uint2 pb = *(const uint2*)&h2h[sb * 64 + l * 4];
                float wa0 = __expf(lrelu(ea.x + ern.x));
                float wa1 = __expf(lrelu(ea.y + ern.y));
                float wb0 = __expf(lrelu(eb.x + ern.x));
                float wb1 = __expf(lrelu(eb.y + ern.y));
                float2 fa0 = h2f(((const __half2*)&pa)[0]);
                float2 fa1 = h2f(((const __half2*)&pa)[1]);
                float2 fb0 = h2f(((const __half2*)&pb)[0]);
                float2 fb1 = h2f(((const __half2*)&pb)[1]);
                a0[0] += wa0 * fa0.x + wb0 * fb0.x;
                a0[1] += wa0 * fa0.y + wb0 * fb0.y;
                a0[2] += wa0 * fa1.x + wb0 * fb1.x;
                a0[3] += wa0 * fa1.y + wb0 * fb1.y;
                a1[0] += wa1 * fa0.x + wb1 * fb0.x;
                a1[1] += wa1 * fa0.y + wb1 * fb0.y;
                a1[2] += wa1 * fa1.x + wb1 * fb1.x;
                a1[3] += wa1 * fa1.y + wb1 * fb1.y;
                den0 += wa0 + wb0;
                den1 += wa1 + wb1;
            }
            for (; i < end; i++) {
                int s = cs[i];
                float2 e = *(const float2*)&elm[s * 4 + half * 2];
                uint2 p = *(const uint2*)&h2h[s * 64 + l * 4];
                float w0 = __expf(lrelu(e.x + ern.x));
                float w1 = __expf(lrelu(e.y + ern.y));
                float2 f0 = h2f(((const __half2*)&p)[0]);
                float2 f1 = h2f(((const __half2*)&p)[1]);
                a0[0] += w0 * f0.x; a0[1] += w0 * f0.y;
                a0[2] += w0 * f1.x; a0[3] += w0 * f1.y;
                a1[0] += w1 * f0.x; a1[1] += w1 * f0.y;
                a1[2] += w1 * f1.x; a1[3] += w1 * f1.y;
                den0 += w0;
                den1 += w1;
            }
        }
        float s0 = 1.0f / fmaxf(den0, 1e-30f);
        float s1 = 1.0f / fmaxf(den1, 1e-30f);
        float4 v0 = {a0[0] * s0, a0[1] * s0, a0[2] * s0, a0[3] * s0};
        float4 v1 = {a1[0] * s1, a1[1] * s1, a1[2] * s1, a1[3] * s1};
        int base = w * 512 + (half * 2) * 128 + et * 64 + l * 4;
        *(float4*)&aggm[base] = v0;
        *(float4*)&aggm[base + 128] = v1;
    }
}

// ---------------- final per-head GEMM: out = aggm @ Bm + bias; + colsum -----
__global__ void __launch_bounds__(256)
gemm_out(const float* __restrict__ aggm, const float* __restrict__ Bm,
         const float* __restrict__ bm, float* __restrict__ out,
         float* __restrict__ colsum) {
    constexpr int TN = 8, TM = 8, BK = 16, BM = 256, BMP = BM + 4;
    __shared__ float xs[BK][BMP];
    __shared__ float ws[BK][64];
    __shared__ float scp[64];

    int tid = threadIdx.x;
    int tx = tid % 8;
    int ty = tid / 8;
    int h = blockIdx.y;
    int r0 = blockIdx.x * BM;
    if (tid < 64) scp[tid] = 0.0f;

    const float* B = Bm + h * (128 * 64);

    unsigned long long acc2[TM][TN / 2];
#pragma unroll
    for (int i = 0; i < TM; i++)
#pragma unroll
        for (int j = 0; j < TN / 2; j++) acc2[i][j] = 0ull;

    for (int kb = 0; kb < 128; kb += BK) {
#pragma unroll
        for (int idx = tid; idx < BM * BK / 4; idx += 256) {
            int lin = idx * 4;
            int r = lin / BK, c = lin % BK;
            int gr = r0 + r;
            float4 v = make_float4(0.f, 0.f, 0.f, 0.f);
            if (gr < NNODES) v = *(const float4*)&aggm[gr * 512 + h * 128 + kb + c];
            xs[c][r] = v.x; xs[c + 1][r] = v.y; xs[c + 2][r] = v.z; xs[c + 3][r] = v.w;
        }
#pragma unroll
        for (int idx = tid; idx < BK * 64 / 4; idx += 256) {
            int lin = idx * 4;
            int r = lin / 64, c = lin % 64;
            *(float4*)&ws[r][c] = *(const float4*)&B[(kb + r) * 64 + c];
        }
        __syncthreads();
#pragma unroll
        for (int kk = 0; kk < BK; kk++) {
            float4 a0 = *(const float4*)&xs[kk][ty * 8];
            float4 a1 = *(const float4*)&xs[kk][ty * 8 + 4];
            const unsigned long long* wp64 =
                (const unsigned long long*)&ws[kk][tx * 8];
            unsigned long long bp0 = wp64[0], bp1 = wp64[1],
                               bp2 = wp64[2], bp3 = wp64[3];
            unsigned long long ap[TM] = {
                bcast2(a0.x), bcast2(a0.y), bcast2(a0.z), bcast2(a0.w),
                bcast2(a1.x), bcast2(a1.y), bcast2(a1.z), bcast2(a1.w)};
#pragma unroll
            for (int i = 0; i < TM; i++) {
                ffma2(acc2[i][0], ap[i], bp0);
                ffma2(acc2[i][1], ap[i], bp1);
                ffma2(acc2[i][2], ap[i], bp2);
                ffma2(acc2[i][3], ap[i], bp3);
            }
        }
        __syncthreads();
    }

    int cb = tx * 8;
    float bias[8];
#pragma unroll
    for (int j = 0; j < 8; j++)
        bias[j] = 0.5f * (bm[h * 64 + cb + j] + bm[256 + h * 64 + cb + j]);

    float colacc[8] = {0.f, 0.f, 0.f, 0.f, 0.f, 0.f, 0.f, 0.f};
#pragma unroll
    for (int i = 0; i < TM; i++) {
        int row = r0 + ty * TM + i;
        float2 u0 = unpack2(acc2[i][0]);
        float2 u1 = unpack2(acc2[i][1]);
        float2 u2 = unpack2(acc2[i][2]);
        float2 u3 = unpack2(acc2[i][3]);
        float av[8] = {u0.x, u0.y, u1.x, u1.y, u2.x, u2.y, u3.x, u3.y};
        if (row < NNODES) {
            float4 o0 = {av[0] + bias[0], av[1] + bias[1], av[2] + bias[2], av[3] + bias[3]};
            float4 o1 = {av[4] + bias[4], av[5] + bias[5], av[6] + bias[6], av[7] + bias[7]};
            *(float4*)&out[row * 256 + h * 64 + cb] = o0;
            *(float4*)&out[row * 256 + h * 64 + cb + 4] = o1;
            colacc[0] += o0.x; colacc[1] += o0.y; colacc[2] += o0.z; colacc[3] += o0.w;
            colacc[4] += o1.x; colacc[5] += o1.y; colacc[6] += o1.z; colacc[7] += o1.w;
        }
    }
#pragma unroll
    for (int j = 0; j < 8; j++) atomicAdd(&scp[cb + j], colacc[j]);
    __syncthreads();
    if (tid < 64) atomicAdd(&colsum[h * 64 + tid], scp[tid]);
}

// ---------------- final centering ----------------
__global__ void center_kernel(float* __restrict__ out, const float* __restrict__ cs) {
    int i = blockIdx.x * blockDim.x + threadIdx.x;
    if (i < NNODES * 256) out[i] -= cs[i & 255] * (1.0f / NNODES);
}

// ---------------- orchestration ----------------
extern "C" void kernel_launch(void* const* d_in, const int* in_sizes, int n_in,
                              void* d_out, int out_size) {
    const float* x   = (const float*)d_in[0];
    const int* src0 = (const int*)d_in[1];
    const int* dst0 = (const int*)d_in[2];
    const int* src1 = (const int*)d_in[3];
    const int* dst1 = (const int*)d_in[4];
    const float* W1  = (const float*)d_in[5];
    const float* al1 = (const float*)d_in[6];
    const float* ar1 = (const float*)d_in[7];
    const float* b1  = (const float*)d_in[8];
    const float* W2  = (const float*)d_in[9];
    const float* al2 = (const float*)d_in[10];
    const float* ar2 = (const float*)d_in[11];
    const float* b2  = (const float*)d_in[12];
    const float* Wm  = (const float*)d_in[13];
    const float* alm = (const float*)d_in[14];
    const float* arm = (const float*)d_in[15];
    const float* bm  = (const float*)d_in[16];
    const float* fc  = (const float*)d_in[17];
    float* out = (float*)d_out;

    __half *zb, *h2h;
    float *h1, *elb, *erb, *elmb, *ermb, *aggm, *wvec, *Bm, *csum;
    int *rpb, *cseb, *wpb, *bsumb;
    cudaGetSymbolAddress((void**)&zb,    g_z);
    cudaGetSymbolAddress((void**)&h1,    g_h1);
    cudaGetSymbolAddress((void**)&h2h,   g_h2h);
    cudaGetSymbolAddress((void**)&elb,   g_el);
    cudaGetSymbolAddress((void**)&erb,   g_er);
    cudaGetSymbolAddress((void**)&elmb,  g_elm);
    cudaGetSymbolAddress((void**)&ermb,  g_erm);
    cudaGetSymbolAddress((void**)&aggm,  g_aggm);
    cudaGetSymbolAddress((void**)&wvec,  g_wvec);
    cudaGetSymbolAddress((void**)&Bm,    g_Bm);
    cudaGetSymbolAddress((void**)&csum,  g_colsum);
    cudaGetSymbolAddress((void**)&rpb,   g_rp);
    cudaGetSymbolAddress((void**)&cseb,  g_cse);
    cudaGetSymbolAddress((void**)&wpb,   g_wp);
    cudaGetSymbolAddress((void**)&bsumb, g_bsum);

    int* rp[2]  = {rpb, rpb + (NNODES + 1)};
    int* cse[2] = {cseb, cseb + NEDGES};
    __half* z[2] = {zb, zb + NNODES * 256};
    float* el[2] = {elb, elb + NNODES * 4};
    float* er[2] = {erb, erb + NNODES * 4};

    const int EG = (NEDGES + 255) / 256;
    const int AGG_BLOCKS = (NNODES * 32 + 255) / 256;

    // ---------------- zero counters + tiny MH precompute -------------------
    zero_int<<<(2 * (NNODES + 1) + 255) / 256, 256>>>(rpb, 2 * (NNODES + 1));
    prep_mh<<<1, 512>>>(Wm, alm, arm, wvec, Bm);

    // ---------------- fused layer-1 GEMM + edge count ----------------------
    const int GEMM1_X = (NNODES + 127) / 128;
    const int COUNT_B = 256;
    gemm1_count<<<dim3(GEMM1_X + COUNT_B, 2), 256>>>(
        x, W1, al1, ar1, zb, elb, erb, dst0, dst1, rpb, GEMM1_X, COUNT_B);

    // ---------------- finish CSR build ----------------
    scan_local<<<dim3(NB_SCAN, 2), CH_SCAN>>>(rpb, bsumb);
    scan_add_wp<<<dim3((NNODES + 255) / 256, 2), 256>>>(rpb, bsumb, wpb);
    fill_k<<<dim3(EG, 2), 256>>>(src0, src1, dst0, dst1, wpb, cseb);

    // ---------------- layer 1 aggregation -> h1 ----------------
    gat_agg128<<<AGG_BLOCKS, 256>>>(
        rp[0], cse[0], rp[1], cse[1], z[0], z[1],
        el[0], er[0], el[1], er[1], b1, h1);

    // ---------------- layer 2: GEMM then agg (+ MH prep fused) -------------
    gemm_att<128, 64, 1><<<dim3((NNODES + 255) / 256, 2), 256>>>(
        h1, W2, al2, ar2, zb, elb, erb);
    gat_agg64_prep<<<AGG_BLOCKS, 256>>>(
        rp[0], cse[0], rp[1], cse[1], z[0], z[1],
        el[0], er[0], el[1], er[1], b2, fc, wvec, h2h, elmb, ermb);

    // ---------------- MH: aggregate raw h2, then per-head GEMM -------------
    gat_agg_mh<<<AGG_BLOCKS, 256>>>(
        rp[0], cse[0], rp[1], cse[1], h2h, elmb, ermb, aggm);
    zero_f<<<1, 256>>>(csum, 256);
    gemm_out<<<dim3((NNODES + 255) / 256, 4), 256>>>(aggm, Bm, bm, out, csum);

    // ---------------- final per-column mean centering -------------------
    center_kernel<<<(NNODES * 256 + 255) / 256, 256>>>(out, csum);
}